// round 11
// baseline (speedup 1.0000x reference)
#include <cuda_runtime.h>
#include <cuda_bf16.h>

#define WARPS_PER_BLOCK 8
#define THREADS_PER_BLOCK (WARPS_PER_BLOCK * 32)

typedef unsigned long long u64;

// ---- packed f32x2 helpers (sm_103a; ptxas never emits FFMA2 from C++) ----
static __device__ __forceinline__ u64 pk(float lo, float hi) {
    u64 r; asm("mov.b64 %0, {%1, %2};" : "=l"(r) : "f"(lo), "f"(hi)); return r;
}
static __device__ __forceinline__ void upk(u64 v, float& lo, float& hi) {
    asm("mov.b64 {%0, %1}, %2;" : "=f"(lo), "=f"(hi) : "l"(v));
}
static __device__ __forceinline__ u64 fma2(u64 a, u64 b, u64 c) {
    u64 r; asm("fma.rn.f32x2 %0, %1, %2, %3;" : "=l"(r) : "l"(a), "l"(b), "l"(c)); return r;
}
static __device__ __forceinline__ u64 mul2(u64 a, u64 b) {
    u64 r; asm("mul.rn.f32x2 %0, %1, %2;" : "=l"(r) : "l"(a), "l"(b)); return r;
}
static __device__ __forceinline__ u64 add2(u64 a, u64 b) {
    u64 r; asm("add.rn.f32x2 %0, %1, %2;" : "=l"(r) : "l"(a), "l"(b)); return r;
}

static __device__ __forceinline__ float merge_f(float a, float b, int w, int lane) {
    const unsigned FULL = 0xffffffffu;
    const float keep = (lane & w) ? b : a;
    const float send = (lane & w) ? a : b;
    return keep + __shfl_xor_sync(FULL, send, w);
}

// One warp per batch row. D=128 floats (row = 32 float4). K=32 (hardwired).
// Octet layout: 4 octets (8 lanes); slot s (0..7): octet o handles candidate
// c = 4s+o, its 512B row read as 4 x 128B chunks (4 lines per LDG.128).
// All reductions deferred past the 8-slot body; dot/norm math in packed f32x2.
__global__ __launch_bounds__(THREADS_PER_BLOCK, 4)
void intra_agg_kernel(const float* __restrict__ features,
                      const int*   __restrict__ nodes,
                      const int*   __restrict__ neighs,
                      const int*   __restrict__ nsamp,
                      float*       __restrict__ out,
                      int B)
{
    const unsigned FULL = 0xffffffffu;
    const int lane = threadIdx.x & 31;
    const int row  = blockIdx.x * WARPS_PER_BLOCK + (threadIdx.x >> 5);
    if (row >= B) return;

    const int ns = nsamp ? nsamp[0] : 10;

    const float4* __restrict__ F = reinterpret_cast<const float4*>(features);
    const int* __restrict__ nrow = neighs + (size_t)row * 32;

    const int my_neigh = nrow[lane];              // lane k owns candidate k
    const int oct      = lane >> 3;               // my octet (0..3)
    const int ol       = lane & 7;                // lane within octet

    // center row in octet-chunk layout, pre-packed as f32x2 pairs
    const float4* cbase = F + (size_t)nodes[row] * 32 + ol;
    u64 cc01[4], cc23[4];
    #pragma unroll
    for (int t = 0; t < 4; t++) {
        const float4 c = cbase[t * 8];
        cc01[t] = pk(c.x, c.y);
        cc23[t] = pk(c.z, c.w);
    }

    // ---- Phase 1: 8 slots, pure LDG + packed-FMA body (no shfl) ----
    const int* __restrict__ ibase = nrow + oct;   // slot s index at ibase[4*s]
    float dp[8], np[8];
    #pragma unroll
    for (int s = 0; s < 8; s++) {
        const int cidx = __ldg(&ibase[4 * s]);    // 1 line, broadcast per octet
        const float4* base = F + (size_t)cidx * 32 + ol;
        float4 f[4];
        #pragma unroll
        for (int t = 0; t < 4; t++) f[t] = base[t * 8];

        u64 a[4], b[4];
        #pragma unroll
        for (int t = 0; t < 4; t++) { a[t] = pk(f[t].x, f[t].y); b[t] = pk(f[t].z, f[t].w); }

        u64 dacc = mul2(cc01[0], a[0]);
        dacc = fma2(cc23[0], b[0], dacc);
        u64 nacc = mul2(a[0], a[0]);
        nacc = fma2(b[0], b[0], nacc);
        #pragma unroll
        for (int t = 1; t < 4; t++) {
            dacc = fma2(cc01[t], a[t], dacc);
            dacc = fma2(cc23[t], b[t], dacc);
            nacc = fma2(a[t], a[t], nacc);
            nacc = fma2(b[t], b[t], nacc);
        }
        float lo, hi;
        upk(dacc, lo, hi); dp[s] = lo + hi;
        upk(nacc, lo, hi); np[s] = lo + hi;
    }

    // ---- One in-octet transpose-reduce of 8 values (w=4,2,1).
    // Lane ol ends holding full octet-sum of slot v = ol; candidate 4s+o
    // lives at warp lane 8*o + s -> owner L reads lane 8*(L&3) + (L>>2). ----
    float my_dot, my_n2;
    {
        float e0 = merge_f(dp[0], dp[4], 4, lane);
        float e1 = merge_f(dp[1], dp[5], 4, lane);
        float e2 = merge_f(dp[2], dp[6], 4, lane);
        float e3 = merge_f(dp[3], dp[7], 4, lane);
        float h0 = merge_f(e0, e2, 2, lane);
        float h1 = merge_f(e1, e3, 2, lane);
        float q  = merge_f(h0, h1, 1, lane);
        my_dot = __shfl_sync(FULL, q, ((lane & 3) << 3) + (lane >> 2));
    }
    {
        float e0 = merge_f(np[0], np[4], 4, lane);
        float e1 = merge_f(np[1], np[5], 4, lane);
        float e2 = merge_f(np[2], np[6], 4, lane);
        float e3 = merge_f(np[3], np[7], 4, lane);
        float h0 = merge_f(e0, e2, 2, lane);
        float h1 = merge_f(e1, e3, 2, lane);
        float q  = merge_f(h0, h1, 1, lane);
        my_n2 = __shfl_sync(FULL, q, ((lane & 3) << 3) + (lane >> 2));
    }

    // key = dot / ||neigh||  (center norm: common positive factor, dropped)
    float r = rsqrtf(my_n2);
    r = r * fmaf(-0.5f * my_n2, r * r, 1.5f);     // Newton -> ~fp32-exact
    const float my_key = my_dot * r;

    // ---- stable rank-by-counting (matches jax.lax.top_k tie-break) ----
    int rank = 0;
    #pragma unroll
    for (int j = 0; j < 32; j++) {
        const float kj = __shfl_sync(FULL, my_key, j);
        rank += (kj > my_key) || (kj == my_key && j < lane);
    }

    // ---- Phase 2: mean over selected neighbors (packed accumulation) ----
    const unsigned sel = __ballot_sync(FULL, rank < ns);
    u64 acc01 = pk(0.f, 0.f), acc23 = pk(0.f, 0.f);

    if (ns == 10) {
        int src10[10];
        unsigned m = sel;
        #pragma unroll
        for (int i = 0; i < 10; i++) { src10[i] = __ffs(m) - 1; m &= m - 1; }
        int nid[10];
        #pragma unroll
        for (int i = 0; i < 10; i++) nid[i] = __shfl_sync(FULL, my_neigh, src10[i]);
        #pragma unroll
        for (int s0 = 0; s0 < 10; s0 += 5) {
            float4 v[5];
            #pragma unroll
            for (int u = 0; u < 5; u++)
                v[u] = F[(size_t)nid[s0 + u] * 32 + lane];
            #pragma unroll
            for (int u = 0; u < 5; u++) {
                acc01 = add2(acc01, pk(v[u].x, v[u].y));
                acc23 = add2(acc23, pk(v[u].z, v[u].w));
            }
        }
    } else {
        unsigned m = sel;
        while (m) {
            const int j = __ffs(m) - 1;
            m &= m - 1;
            const int nidx = __shfl_sync(FULL, my_neigh, j);
            const float4 v = F[(size_t)nidx * 32 + lane];
            acc01 = add2(acc01, pk(v.x, v.y));
            acc23 = add2(acc23, pk(v.z, v.w));
        }
    }

    const float inv = 1.0f / (float)ns;
    float ax, ay, az, aw;
    upk(acc01, ax, ay);
    upk(acc23, az, aw);
    float4 o;
    o.x = fmaxf(ax * inv, 0.0f);
    o.y = fmaxf(ay * inv, 0.0f);
    o.z = fmaxf(az * inv, 0.0f);
    o.w = fmaxf(aw * inv, 0.0f);
    __stcs(reinterpret_cast<float4*>(out) + (size_t)row * 32 + lane, o);
}

extern "C" void kernel_launch(void* const* d_in, const int* in_sizes, int n_in,
                              void* d_out, int out_size)
{
    const float* features = (const float*)d_in[0];
    const int*   nodes    = (const int*)d_in[1];
    const int*   neighs   = (const int*)d_in[2];
    const int*   nsamp    = (n_in >= 4) ? (const int*)d_in[3] : nullptr;
    float*       out      = (float*)d_out;

    const int B = in_sizes[1];

    const int blocks = (B + WARPS_PER_BLOCK - 1) / WARPS_PER_BLOCK;
    intra_agg_kernel<<<blocks, THREADS_PER_BLOCK>>>(features, nodes, neighs, nsamp,
                                                    out, B);
}

// round 12
// speedup vs baseline: 1.3570x; 1.3570x over previous
#include <cuda_runtime.h>
#include <cuda_bf16.h>

#define WARPS_PER_BLOCK 8
#define THREADS_PER_BLOCK (WARPS_PER_BLOCK * 32)

// float4 global load with L1 evict-last priority (lines with known reuse).
static __device__ __forceinline__ float4 ldg_evict_last(const float4* p) {
    float4 v;
    asm("ld.global.L1::evict_last.v4.f32 {%0,%1,%2,%3}, [%4];"
        : "=f"(v.x), "=f"(v.y), "=f"(v.z), "=f"(v.w) : "l"(p));
    return v;
}

static __device__ __forceinline__ float merge_f(float a, float b, int w, int lane) {
    const unsigned FULL = 0xffffffffu;
    const float keep = (lane & w) ? b : a;
    const float send = (lane & w) ? a : b;
    return keep + __shfl_xor_sync(FULL, send, w);
}

// One warp per batch row. D=128 floats (row = 32 float4). K=32 (hardwired).
// Octet layout: 4 octets (8 lanes); slot s (0..7): octet o handles candidate
// c = 4s+o, its 512B row read as 4 x 128B chunks (4 lines per LDG.128).
// All reductions deferred past the 8-slot body; L1 replacement steered:
// phase-1 rows evict_last (phase-2 reuses 10/32), phase-2/center last-use.
__global__ __launch_bounds__(THREADS_PER_BLOCK, 4)
void intra_agg_kernel(const float* __restrict__ features,
                      const int*   __restrict__ nodes,
                      const int*   __restrict__ neighs,
                      const int*   __restrict__ nsamp,
                      float*       __restrict__ out,
                      int B)
{
    const unsigned FULL = 0xffffffffu;
    const int lane = threadIdx.x & 31;
    const int row  = blockIdx.x * WARPS_PER_BLOCK + (threadIdx.x >> 5);
    if (row >= B) return;

    const int ns = nsamp ? nsamp[0] : 10;

    const float4* __restrict__ F = reinterpret_cast<const float4*>(features);
    const int* __restrict__ nrow = neighs + (size_t)row * 32;

    const int my_neigh = nrow[lane];              // lane k owns candidate k
    const int oct      = lane >> 3;               // my octet (0..3)
    const int ol       = lane & 7;                // lane within octet

    // center row (consumed into registers; last-use, don't pollute L1)
    const float4* cbase = F + (size_t)nodes[row] * 32 + ol;
    float4 cc[4];
    #pragma unroll
    for (int t = 0; t < 4; t++) cc[t] = __ldlu(&cbase[t * 8]);

    // ---- Phase 1: 8 slots, pure LDG+FMA (no shfl in the body) ----
    const int* __restrict__ ibase = nrow + oct;   // slot s index at ibase[4*s]
    float dp[8], np[8];
    #pragma unroll
    for (int s = 0; s < 8; s++) {
        const int cidx = __ldg(&ibase[4 * s]);    // 1 line, broadcast per octet
        const float4* base = F + (size_t)cidx * 32 + ol;
        float4 f[4];
        #pragma unroll
        for (int t = 0; t < 4; t++) f[t] = ldg_evict_last(&base[t * 8]);

        float d = 0.0f, n = 0.0f;
        #pragma unroll
        for (int t = 0; t < 4; t++) {
            d = fmaf(cc[t].x, f[t].x, d);
            d = fmaf(cc[t].y, f[t].y, d);
            d = fmaf(cc[t].z, f[t].z, d);
            d = fmaf(cc[t].w, f[t].w, d);
            n = fmaf(f[t].x, f[t].x, n);
            n = fmaf(f[t].y, f[t].y, n);
            n = fmaf(f[t].z, f[t].z, n);
            n = fmaf(f[t].w, f[t].w, n);
        }
        dp[s] = d; np[s] = n;
    }

    // ---- One in-octet transpose-reduce of 8 values (w=4,2,1).
    // Lane ol ends holding the full octet-sum of slot v = ol; candidate
    // c = 4s+o lives at warp lane 8*o+s -> owner L reads lane 8*(L&3)+(L>>2). ----
    float my_dot, my_n2;
    {
        float e0 = merge_f(dp[0], dp[4], 4, lane);
        float e1 = merge_f(dp[1], dp[5], 4, lane);
        float e2 = merge_f(dp[2], dp[6], 4, lane);
        float e3 = merge_f(dp[3], dp[7], 4, lane);
        float h0 = merge_f(e0, e2, 2, lane);
        float h1 = merge_f(e1, e3, 2, lane);
        float q  = merge_f(h0, h1, 1, lane);
        my_dot = __shfl_sync(FULL, q, ((lane & 3) << 3) + (lane >> 2));
    }
    {
        float e0 = merge_f(np[0], np[4], 4, lane);
        float e1 = merge_f(np[1], np[5], 4, lane);
        float e2 = merge_f(np[2], np[6], 4, lane);
        float e3 = merge_f(np[3], np[7], 4, lane);
        float h0 = merge_f(e0, e2, 2, lane);
        float h1 = merge_f(e1, e3, 2, lane);
        float q  = merge_f(h0, h1, 1, lane);
        my_n2 = __shfl_sync(FULL, q, ((lane & 3) << 3) + (lane >> 2));
    }

    // key = dot / ||neigh||  (center norm: common positive factor, dropped)
    float r = rsqrtf(my_n2);
    r = r * fmaf(-0.5f * my_n2, r * r, 1.5f);     // Newton -> ~fp32-exact
    const float my_key = my_dot * r;

    // ---- stable rank-by-counting (matches jax.lax.top_k tie-break) ----
    int rank = 0;
    #pragma unroll
    for (int j = 0; j < 32; j++) {
        const float kj = __shfl_sync(FULL, my_key, j);
        rank += (kj > my_key) || (kj == my_key && j < lane);
    }

    // ---- Phase 2: mean over selected neighbors (last-use loads) ----
    const unsigned sel = __ballot_sync(FULL, rank < ns);
    float4 acc = make_float4(0.f, 0.f, 0.f, 0.f);

    if (ns == 10) {
        int src10[10];
        unsigned m = sel;
        #pragma unroll
        for (int i = 0; i < 10; i++) { src10[i] = __ffs(m) - 1; m &= m - 1; }
        int nid[10];
        #pragma unroll
        for (int i = 0; i < 10; i++) nid[i] = __shfl_sync(FULL, my_neigh, src10[i]);
        #pragma unroll
        for (int s0 = 0; s0 < 10; s0 += 5) {
            float4 v[5];
            #pragma unroll
            for (int u = 0; u < 5; u++)
                v[u] = __ldlu(&F[(size_t)nid[s0 + u] * 32 + lane]);
            #pragma unroll
            for (int u = 0; u < 5; u++) {
                acc.x += v[u].x; acc.y += v[u].y;
                acc.z += v[u].z; acc.w += v[u].w;
            }
        }
    } else {
        unsigned m = sel;
        while (m) {
            const int j = __ffs(m) - 1;
            m &= m - 1;
            const int nidx = __shfl_sync(FULL, my_neigh, j);
            const float4 v = __ldlu(&F[(size_t)nidx * 32 + lane]);
            acc.x += v.x; acc.y += v.y; acc.z += v.z; acc.w += v.w;
        }
    }

    const float inv = 1.0f / (float)ns;
    float4 o;
    o.x = fmaxf(acc.x * inv, 0.0f);
    o.y = fmaxf(acc.y * inv, 0.0f);
    o.z = fmaxf(acc.z * inv, 0.0f);
    o.w = fmaxf(acc.w * inv, 0.0f);
    __stcs(reinterpret_cast<float4*>(out) + (size_t)row * 32 + lane, o);
}

extern "C" void kernel_launch(void* const* d_in, const int* in_sizes, int n_in,
                              void* d_out, int out_size)
{
    const float* features = (const float*)d_in[0];
    const int*   nodes    = (const int*)d_in[1];
    const int*   neighs   = (const int*)d_in[2];
    const int*   nsamp    = (n_in >= 4) ? (const int*)d_in[3] : nullptr;
    float*       out      = (float*)d_out;

    const int B = in_sizes[1];

    const int blocks = (B + WARPS_PER_BLOCK - 1) / WARPS_PER_BLOCK;
    intra_agg_kernel<<<blocks, THREADS_PER_BLOCK>>>(features, nodes, neighs, nsamp,
                                                    out, B);
}

// round 13
// speedup vs baseline: 1.4025x; 1.0335x over previous
#include <cuda_runtime.h>
#include <cuda_bf16.h>

#define WARPS_PER_BLOCK 8
#define THREADS_PER_BLOCK (WARPS_PER_BLOCK * 32)

static __device__ __forceinline__ float merge_f(float a, float b, int w, int lane) {
    const unsigned FULL = 0xffffffffu;
    const float keep = (lane & w) ? b : a;
    const float send = (lane & w) ? a : b;
    return keep + __shfl_xor_sync(FULL, send, w);
}

// One warp per batch row. D=128 floats (row = 32 float4). K=32 (hardwired).
// Octet layout: 4 octets (8 lanes); slot s (0..7): octet o handles candidate
// c = 4s+o, its 512B row read as 4 x 128B chunks (4 lines per LDG.128).
// All reductions deferred past the 8-slot body (pure LDG+FMA). Rank + phase-2
// index fetch via smem broadcast (uniform LDS) instead of shfl loops.
__global__ __launch_bounds__(THREADS_PER_BLOCK, 4)
void intra_agg_kernel(const float* __restrict__ features,
                      const int*   __restrict__ nodes,
                      const int*   __restrict__ neighs,
                      const int*   __restrict__ nsamp,
                      float*       __restrict__ out,
                      int B)
{
    const unsigned FULL = 0xffffffffu;
    const int lane = threadIdx.x & 31;
    const int wid  = threadIdx.x >> 5;
    const int row  = blockIdx.x * WARPS_PER_BLOCK + wid;
    if (row >= B) return;

    __shared__ float skey[WARPS_PER_BLOCK][32];
    __shared__ int   sngh[WARPS_PER_BLOCK][32];

    const int ns = nsamp ? nsamp[0] : 10;

    const float4* __restrict__ F = reinterpret_cast<const float4*>(features);
    const int* __restrict__ nrow = neighs + (size_t)row * 32;

    const int my_neigh = nrow[lane];              // lane k owns candidate k
    sngh[wid][lane] = my_neigh;                   // for phase-2 index fetch
    const int oct = lane >> 3;                    // my octet (0..3)
    const int ol  = lane & 7;                     // lane within octet

    // center row in octet-chunk layout: cc[t] = float4 index t*8 + ol
    const float4* cbase = F + (size_t)nodes[row] * 32 + ol;
    float4 cc[4];
    #pragma unroll
    for (int t = 0; t < 4; t++) cc[t] = cbase[t * 8];

    // ---- Phase 1: 8 slots, pure LDG+FMA (no shfl in the body) ----
    const int* __restrict__ ibase = nrow + oct;   // slot s index at ibase[4*s]
    float dp[8], np[8];
    #pragma unroll
    for (int s = 0; s < 8; s++) {
        const int cidx = __ldg(&ibase[4 * s]);    // 1 line, broadcast per octet
        const float4* base = F + (size_t)cidx * 32 + ol;
        float4 f[4];
        #pragma unroll
        for (int t = 0; t < 4; t++) f[t] = base[t * 8];

        float d = 0.0f, n = 0.0f;
        #pragma unroll
        for (int t = 0; t < 4; t++) {
            d = fmaf(cc[t].x, f[t].x, d);
            d = fmaf(cc[t].y, f[t].y, d);
            d = fmaf(cc[t].z, f[t].z, d);
            d = fmaf(cc[t].w, f[t].w, d);
            n = fmaf(f[t].x, f[t].x, n);
            n = fmaf(f[t].y, f[t].y, n);
            n = fmaf(f[t].z, f[t].z, n);
            n = fmaf(f[t].w, f[t].w, n);
        }
        dp[s] = d; np[s] = n;
    }

    // ---- One in-octet transpose-reduce of 8 values (w=4,2,1).
    // Lane ol ends holding the full octet-sum of slot v = ol; candidate
    // c = 4s+o lives at warp lane 8*o+s -> owner L reads lane 8*(L&3)+(L>>2). ----
    float my_dot, my_n2;
    {
        float e0 = merge_f(dp[0], dp[4], 4, lane);
        float e1 = merge_f(dp[1], dp[5], 4, lane);
        float e2 = merge_f(dp[2], dp[6], 4, lane);
        float e3 = merge_f(dp[3], dp[7], 4, lane);
        float h0 = merge_f(e0, e2, 2, lane);
        float h1 = merge_f(e1, e3, 2, lane);
        float q  = merge_f(h0, h1, 1, lane);
        my_dot = __shfl_sync(FULL, q, ((lane & 3) << 3) + (lane >> 2));
    }
    {
        float e0 = merge_f(np[0], np[4], 4, lane);
        float e1 = merge_f(np[1], np[5], 4, lane);
        float e2 = merge_f(np[2], np[6], 4, lane);
        float e3 = merge_f(np[3], np[7], 4, lane);
        float h0 = merge_f(e0, e2, 2, lane);
        float h1 = merge_f(e1, e3, 2, lane);
        float q  = merge_f(h0, h1, 1, lane);
        my_n2 = __shfl_sync(FULL, q, ((lane & 3) << 3) + (lane >> 2));
    }

    // key = dot / ||neigh||  (center norm: common positive factor, dropped)
    float r = rsqrtf(my_n2);
    r = r * fmaf(-0.5f * my_n2, r * r, 1.5f);     // Newton -> ~fp32-exact
    const float my_key = my_dot * r;

    // ---- stable rank via smem broadcast (ties broken by lower index,
    //      matching jax.lax.top_k) ----
    skey[wid][lane] = my_key;
    __syncwarp();
    int rank = 0;
    const float4* kp = reinterpret_cast<const float4*>(skey[wid]);
    #pragma unroll
    for (int jj = 0; jj < 8; jj++) {
        const float4 kv = kp[jj];                 // uniform LDS.128 broadcast
        const int j = jj * 4;
        rank += (kv.x > my_key) || (kv.x == my_key && (j + 0) < lane);
        rank += (kv.y > my_key) || (kv.y == my_key && (j + 1) < lane);
        rank += (kv.z > my_key) || (kv.z == my_key && (j + 2) < lane);
        rank += (kv.w > my_key) || (kv.w == my_key && (j + 3) < lane);
    }

    // ---- Phase 2: mean over selected neighbors ----
    const unsigned sel = __ballot_sync(FULL, rank < ns);
    float4 acc = make_float4(0.f, 0.f, 0.f, 0.f);

    if (ns == 10) {
        int src10[10];
        unsigned m = sel;
        #pragma unroll
        for (int i = 0; i < 10; i++) { src10[i] = __ffs(m) - 1; m &= m - 1; }
        int nid[10];
        #pragma unroll
        for (int i = 0; i < 10; i++) nid[i] = sngh[wid][src10[i]];  // uniform LDS
        #pragma unroll
        for (int s0 = 0; s0 < 10; s0 += 5) {
            float4 v[5];
            #pragma unroll
            for (int u = 0; u < 5; u++)
                v[u] = F[(size_t)nid[s0 + u] * 32 + lane];
            #pragma unroll
            for (int u = 0; u < 5; u++) {
                acc.x += v[u].x; acc.y += v[u].y;
                acc.z += v[u].z; acc.w += v[u].w;
            }
        }
    } else {
        unsigned m = sel;
        while (m) {
            const int j = __ffs(m) - 1;
            m &= m - 1;
            const int nidx = sngh[wid][j];
            const float4 v = F[(size_t)nidx * 32 + lane];
            acc.x += v.x; acc.y += v.y; acc.z += v.z; acc.w += v.w;
        }
    }

    const float inv = 1.0f / (float)ns;
    float4 o;
    o.x = fmaxf(acc.x * inv, 0.0f);
    o.y = fmaxf(acc.y * inv, 0.0f);
    o.z = fmaxf(acc.z * inv, 0.0f);
    o.w = fmaxf(acc.w * inv, 0.0f);
    __stcs(reinterpret_cast<float4*>(out) + (size_t)row * 32 + lane, o);
}

extern "C" void kernel_launch(void* const* d_in, const int* in_sizes, int n_in,
                              void* d_out, int out_size)
{
    const float* features = (const float*)d_in[0];
    const int*   nodes    = (const int*)d_in[1];
    const int*   neighs   = (const int*)d_in[2];
    const int*   nsamp    = (n_in >= 4) ? (const int*)d_in[3] : nullptr;
    float*       out      = (float*)d_out;

    const int B = in_sizes[1];

    const int blocks = (B + WARPS_PER_BLOCK - 1) / WARPS_PER_BLOCK;
    intra_agg_kernel<<<blocks, THREADS_PER_BLOCK>>>(features, nodes, neighs, nsamp,
                                                    out, B);
}